// round 5
// baseline (speedup 1.0000x reference)
#include <cuda_runtime.h>
#include <math.h>

#define NLM 25
#define NPATH 65
#define PENT_STRIDE 320
#define SEG_STRIDE 9
#define PI_F 3.14159265358979323846f
#define CUTOFF_F 5.0f
#define MAXN 10240

// ---------------- scratch (static __device__, no allocations) ----------------
__device__ float  g_y0[MAXN * NLM * 16];
__device__ float  g_y1[MAXN * 2 * NLM * 64];
__device__ float  g_y2[MAXN * 2 * NLM * 64];
__device__ double g_Cc[NLM * NLM * NLM];
__device__ float  g_CG[NLM * NLM * NLM];
__device__ double g_Ure[NLM * NLM];
__device__ double g_Uim[NLM * NLM];
__device__ int2   g_pent[NPATH * PENT_STRIDE];   // (aoff | boff<<16, cg bits); off = idx*256
__device__ int    g_pseg[NPATH * SEG_STRIDE];    // c | cnt<<8  (cnt multiple of 4)
__device__ int    g_psegcnt[NPATH];
__device__ int    g_pathS[NPATH];

__constant__ int c_deg[NLM] = {0,1,1,1,2,2,2,2,2,3,3,3,3,3,3,3,4,4,4,4,4,4,4,4,4};

// ---------------- packed f32x2 helpers ----------------
__device__ __forceinline__ void fma2_(float2& t, float2 a, float2 b) {
    asm("{\n\t.reg .b64 ra, rb, rt;\n\t"
        "mov.b64 ra, {%2, %3};\n\t"
        "mov.b64 rb, {%4, %5};\n\t"
        "mov.b64 rt, {%0, %1};\n\t"
        "fma.rn.f32x2 rt, ra, rb, rt;\n\t"
        "mov.b64 {%0, %1}, rt;\n\t}"
        : "+f"(t.x), "+f"(t.y)
        : "f"(a.x), "f"(a.y), "f"(b.x), "f"(b.y));
}
__device__ __forceinline__ float2 mul2_(float2 a, float2 b) {
    float2 d;
    asm("{\n\t.reg .b64 ra, rb, rd;\n\t"
        "mov.b64 ra, {%2, %3};\n\t"
        "mov.b64 rb, {%4, %5};\n\t"
        "mul.rn.f32x2 rd, ra, rb;\n\t"
        "mov.b64 {%0, %1}, rd;\n\t}"
        : "=f"(d.x), "=f"(d.y)
        : "f"(a.x), "f"(a.y), "f"(b.x), "f"(b.y));
    return d;
}

// ---------------- CG construction ----------------
__device__ __forceinline__ double dfact(int n) {
    const double f[16] = {1.0,1.0,2.0,6.0,24.0,120.0,720.0,5040.0,40320.0,
                          362880.0,3628800.0,39916800.0,479001600.0,
                          6227020800.0,87178291200.0,1307674368000.0};
    return f[n];
}

__device__ double cg_complex(int l1,int m1,int l2,int m2,int l3,int m3) {
    if (m1 + m2 != m3 || l3 < abs(l1 - l2) || l3 > l1 + l2) return 0.0;
    double P = dfact(l1+l2-l3) * dfact(l1-l2+l3) * dfact(-l1+l2+l3) / dfact(l1+l2+l3+1)
             * dfact(l1+m1) * dfact(l1-m1) * dfact(l2+m2) * dfact(l2-m2)
             * dfact(l3+m3) * dfact(l3-m3);
    double sp = sqrt(P);
    int kmin = max(0, max(l2 - l3 - m1, l1 - l3 + m2));
    int kmax = min(l1 + l2 - l3, min(l1 - m1, l2 + m2));
    double s = 0.0;
    for (int k = kmin; k <= kmax; k++) {
        double D = dfact(k) * dfact(l1+l2-l3-k) * dfact(l1-m1-k) * dfact(l2+m2-k)
                 * dfact(l3-l2+m1+k) * dfact(l3-l1-m2+k);
        s += ((k & 1) ? -1.0 : 1.0) * sp / D;
    }
    return sqrt(2.0 * l3 + 1.0) * s;
}

__global__ void k_init_u() {
    int t = threadIdx.x;
    for (int q = t; q < NLM * NLM; q += blockDim.x) { g_Ure[q] = 0.0; g_Uim[q] = 0.0; }
    __syncthreads();
    if (t == 0) {
        const double is2 = 0.7071067811865476;
        for (int l = 0; l <= 4; l++) {
            int off = l * l + l;
            g_Ure[off * NLM + off] = 1.0;
            for (int m = 1; m <= l; m++) {
                double sgn = (m & 1) ? -1.0 : 1.0;
                g_Ure[(off + m) * NLM + (off + m)] = sgn * is2;
                g_Ure[(off + m) * NLM + (off - m)] = is2;
                g_Uim[(off - m) * NLM + (off - m)] = is2;
                g_Uim[(off - m) * NLM + (off + m)] = -sgn * is2;
            }
        }
    }
}

__global__ void k_init_cc() {
    int t = blockIdx.x * blockDim.x + threadIdx.x;
    if (t >= NLM * NLM * NLM) return;
    int a = t / (NLM * NLM), b = (t / NLM) % NLM, c = t % NLM;
    int l1 = c_deg[a], m1 = a - l1 * l1 - l1;
    int l2 = c_deg[b], m2 = b - l2 * l2 - l2;
    int l3 = c_deg[c], m3 = c - l3 * l3 - l3;
    g_Cc[t] = cg_complex(l1, m1, l2, m2, l3, m3);
}

__global__ void k_init_T() {
    int t = blockIdx.x * blockDim.x + threadIdx.x;
    if (t >= NLM * NLM * NLM) return;
    int i = t / (NLM * NLM), j = (t / NLM) % NLM, k = t % NLM;
    int li = c_deg[i], mi = i - li * li - li;
    int lj = c_deg[j], mj = j - lj * lj - lj;
    int lk = c_deg[k], mk = k - lk * lk - lk;
    int acols[2] = {i, li * li + li - mi}; int na = mi ? 2 : 1;
    int bcols[2] = {j, lj * lj + lj - mj}; int nb = mj ? 2 : 1;
    int ccols[2] = {k, lk * lk + lk - mk}; int nc = mk ? 2 : 1;
    double tre = 0.0, tim = 0.0;
    for (int aa = 0; aa < na; aa++) {
        int a = acols[aa];
        double ur1 = g_Ure[i * NLM + a], ui1 = g_Uim[i * NLM + a];
        for (int bb = 0; bb < nb; bb++) {
            int b = bcols[bb];
            double ur2 = g_Ure[j * NLM + b], ui2 = g_Uim[j * NLM + b];
            double wre = ur1 * ur2 - ui1 * ui2;
            double wim = ur1 * ui2 + ui1 * ur2;
            for (int cc = 0; cc < nc; cc++) {
                int c = ccols[cc];
                double cval = g_Cc[(a * NLM + b) * NLM + c];
                if (cval == 0.0) continue;
                double ur3 = g_Ure[k * NLM + c], ui3 = -g_Uim[k * NLM + c];
                tre += (wre * ur3 - wim * ui3) * cval;
                tim += (wre * ui3 + wim * ur3) * cval;
            }
        }
    }
    double v = tre + tim;
    g_CG[t] = (fabs(v) < 1e-12) ? 0.0f : (float)v;
}

// warp-per-path ballot compaction; entries padded to multiples of 4
__global__ void k_init_ents() {
    int p = blockIdx.x;
    int lane = threadIdx.x;
    // decode path
    int l1 = 0, l2 = 0, l3 = 0, acc = 0;
    bool found = false;
    for (int a1 = 0; a1 <= 4; a1++)
        for (int a2 = 0; a2 <= 4; a2++) {
            int lo = abs(a1 - a2), hi = min(4, a1 + a2), cnt = hi - lo + 1;
            if (!found) {
                if (p < acc + cnt) { l1 = a1; l2 = a2; l3 = lo + (p - acc); found = true; }
                else acc += cnt;
            }
        }
    if (lane == 0) g_pathS[p] = (l1 + l2 + l3) & 1;

    int na = 2 * l1 + 1, nb = 2 * l2 + 1, npair = na * nb;
    int a0 = l1 * l1, b0 = l2 * l2;
    int eb = p * PENT_STRIDE;
    int ne = 0, ns = 0;
    for (int c = l3 * l3; c < (l3 + 1) * (l3 + 1); c++) {
        int segstart = ne;
        for (int base = 0; base < npair; base += 32) {
            int q = base + lane;
            float v = 0.0f; int a = 0, b = 0;
            if (q < npair) {
                a = a0 + q / nb; b = b0 + q % nb;
                v = g_CG[(a * NLM + b) * NLM + c];
            }
            unsigned mask = __ballot_sync(0xffffffffu, v != 0.0f);
            if (v != 0.0f) {
                int pos = ne + __popc(mask & ((1u << lane) - 1u));
                g_pent[eb + pos] = make_int2((a * 256) | ((b * 256) << 16), __float_as_int(v));
            }
            ne += __popc(mask);
        }
        int cn = ne - segstart;
        int pad = (4 - (cn & 3)) & 3;
        if (cn > 0) {
            if (lane < pad) g_pent[eb + ne + lane] = make_int2(0, 0);
            ne += pad; cn += pad;
            if (lane == 0) g_pseg[p * SEG_STRIDE + ns] = c | (cn << 8);
            ns++;
        }
    }
    if (lane == 0) g_psegcnt[p] = ns;
}

// ---------------- stage kernels ----------------
__global__ void k_zero(int total4) {
    int t = blockIdx.x * blockDim.x + threadIdx.x;
    if (t < total4) ((float4*)g_y0)[t] = make_float4(0.f, 0.f, 0.f, 0.f);
}

// 16 lanes per edge; each lane computes ONE rbf exp, shared via shuffle
__global__ void k_edge(const int* __restrict__ nbr, const float* __restrict__ disp,
                       const int* __restrict__ Z, const float* __restrict__ Wsp,
                       const float* __restrict__ normp, int E) {
    int t = blockIdx.x * blockDim.x + threadIdx.x;
    int e = t >> 4, lane = t & 15;
    // E*16 is an exact multiple of 256 for this problem; guard anyway without
    // exiting before shuffles only if the block is full:
    bool valid = (e < E);
    int i = 0, j = 0;
    float dx = 0.f, dy = 0.f, dz = 1.f;
    if (valid) {
        i = nbr[2 * e]; j = nbr[2 * e + 1];
        dx = disp[3 * e]; dy = disp[3 * e + 1]; dz = disp[3 * e + 2];
    }
    float r = sqrtf(dx * dx + dy * dy + dz * dz + 1e-12f);
    float inv = 1.0f / r;
    float x = dx * inv, y = dy * inv, z = dz * inv;
    bool ok = valid && (r < CUTOFF_F);
    float fcut = 0.5f * (cosf(PI_F * fminf(r * (1.0f / CUTOFF_F), 1.0f)) + 1.0f);

    int Zj = valid ? Z[j] : 0;
    const float gamma = 10.24f;
    float d = r - (float)lane * (CUTOFF_F / 15.0f);
    float rbf = expf(-gamma * d * d);

    const float* W = Wsp + Zj * 256 + lane;
    float gsum = 0.0f;
#pragma unroll
    for (int k = 0; k < 16; k++) {
        float rb = __shfl_sync(0xffffffffu, rbf, k, 16);
        gsum = fmaf(rb, W[k * 16], gsum);
    }
    if (!ok) return;
    float g = gsum * fcut / normp[0];

    float x2 = x * x, y2 = y * y, z2 = z * z;
    float Y[NLM];
    Y[0]  = 0.5f * sqrtf(1.0f / PI_F);
    Y[1]  = sqrtf(3.0f / (4.0f * PI_F)) * y;
    Y[2]  = sqrtf(3.0f / (4.0f * PI_F)) * z;
    Y[3]  = sqrtf(3.0f / (4.0f * PI_F)) * x;
    Y[4]  = 0.5f * sqrtf(15.0f / PI_F) * x * y;
    Y[5]  = 0.5f * sqrtf(15.0f / PI_F) * y * z;
    Y[6]  = 0.25f * sqrtf(5.0f / PI_F) * (3.0f * z2 - 1.0f);
    Y[7]  = 0.5f * sqrtf(15.0f / PI_F) * x * z;
    Y[8]  = 0.25f * sqrtf(15.0f / PI_F) * (x2 - y2);
    Y[9]  = 0.25f * sqrtf(35.0f / (2.0f * PI_F)) * y * (3.0f * x2 - y2);
    Y[10] = 0.5f * sqrtf(105.0f / PI_F) * x * y * z;
    Y[11] = 0.25f * sqrtf(21.0f / (2.0f * PI_F)) * y * (5.0f * z2 - 1.0f);
    Y[12] = 0.25f * sqrtf(7.0f / PI_F) * z * (5.0f * z2 - 3.0f);
    Y[13] = 0.25f * sqrtf(21.0f / (2.0f * PI_F)) * x * (5.0f * z2 - 1.0f);
    Y[14] = 0.25f * sqrtf(105.0f / PI_F) * z * (x2 - y2);
    Y[15] = 0.25f * sqrtf(35.0f / (2.0f * PI_F)) * x * (x2 - 3.0f * y2);
    Y[16] = 0.75f * sqrtf(35.0f / PI_F) * x * y * (x2 - y2);
    Y[17] = 0.75f * sqrtf(35.0f / (2.0f * PI_F)) * y * z * (3.0f * x2 - y2);
    Y[18] = 0.75f * sqrtf(5.0f / PI_F) * x * y * (7.0f * z2 - 1.0f);
    Y[19] = 0.75f * sqrtf(5.0f / (2.0f * PI_F)) * y * z * (7.0f * z2 - 3.0f);
    Y[20] = (3.0f / 16.0f) * sqrtf(1.0f / PI_F) * (35.0f * z2 * z2 - 30.0f * z2 + 3.0f);
    Y[21] = 0.75f * sqrtf(5.0f / (2.0f * PI_F)) * x * z * (7.0f * z2 - 3.0f);
    Y[22] = (3.0f / 8.0f) * sqrtf(5.0f / PI_F) * (x2 - y2) * (7.0f * z2 - 1.0f);
    Y[23] = 0.75f * sqrtf(35.0f / (2.0f * PI_F)) * x * z * (x2 - 3.0f * y2);
    Y[24] = (3.0f / 16.0f) * sqrtf(35.0f / PI_F) * (x2 * x2 - 6.0f * x2 * y2 + y2 * y2);

    float* dst = g_y0 + (size_t)i * (NLM * 16) + lane;
#pragma unroll
    for (int lm = 0; lm < NLM; lm++)
        atomicAdd(dst + lm * 16, Y[lm] * g);
}

// ---- TP layer 0: 128 threads, role 0 -> sa(W1), role 1 -> sb(W2); paths split by role ----
__global__ void __launch_bounds__(128) k_tp0(const float* __restrict__ W1,
                                             const float* __restrict__ W2,
                                             const float* __restrict__ wp) {
    __shared__ float sa[NLM * 64];
    __shared__ float sb[NLM * 64];
    __shared__ float sout[2 * NLM * 64];
    int n = blockIdx.x;
    int tid = threadIdx.x;
    int g = tid & 63;
    int role = tid >> 6;

    const float* yin = g_y0 + (size_t)n * (NLM * 16);
    const float* Wm = role ? W2 : W1;
    float* dst = role ? sb : sa;

    for (int q = tid; q < 2 * NLM * 64; q += 128) sout[q] = 0.0f;

    for (int d = 0; d < 5; d++) {
        float w[16];
        const float* Wb = Wm + (d * 16) * 64 + g;
#pragma unroll
        for (int f = 0; f < 16; f++) w[f] = Wb[f * 64];
        for (int lm = d * d; lm < (d + 1) * (d + 1); lm++) {
            const float4* s4 = (const float4*)(yin + lm * 16);
            float a0 = 0.f, a1 = 0.f, a2 = 0.f, a3 = 0.f;
#pragma unroll
            for (int k = 0; k < 4; k++) {
                float4 v = s4[k];
                a0 = fmaf(v.x, w[4*k+0], a0);
                a1 = fmaf(v.y, w[4*k+1], a1);
                a2 = fmaf(v.z, w[4*k+2], a2);
                a3 = fmaf(v.w, w[4*k+3], a3);
            }
            dst[lm * 64 + g] = (a0 + a1) + (a2 + a3);
        }
    }
    __syncthreads();

    const char* sab = (const char*)sa + 4 * g;
    const char* sbb = (const char*)sb + 4 * g;
    for (int p = role; p < NPATH; p += 2) {
        float w00 = wp[p * 256 + g];
        int s = g_pathS[p];
        int eb = p * PENT_STRIDE;
        int ns = g_psegcnt[p];
        for (int sg = 0; sg < ns; sg++) {
            int sc = g_pseg[p * SEG_STRIDE + sg];
            int c = sc & 255, cnt = sc >> 8;
            const int4* ge = (const int4*)(g_pent + eb);
            float t0 = 0.f, t1 = 0.f;
            for (int k = 0; k < cnt; k += 4) {
                int4 u0 = ge[k >> 1];
                int4 u1 = ge[(k >> 1) + 1];
                {
                    float va = *(const float*)(sab + (u0.x & 0xFFFF));
                    float vb = *(const float*)(sbb + (u0.x >> 16));
                    t0 = fmaf(__int_as_float(u0.y) * va, vb, t0);
                }
                {
                    float va = *(const float*)(sab + (u0.z & 0xFFFF));
                    float vb = *(const float*)(sbb + (u0.z >> 16));
                    t1 = fmaf(__int_as_float(u0.w) * va, vb, t1);
                }
                {
                    float va = *(const float*)(sab + (u1.x & 0xFFFF));
                    float vb = *(const float*)(sbb + (u1.x >> 16));
                    t0 = fmaf(__int_as_float(u1.y) * va, vb, t0);
                }
                {
                    float va = *(const float*)(sab + (u1.z & 0xFFFF));
                    float vb = *(const float*)(sbb + (u1.z >> 16));
                    t1 = fmaf(__int_as_float(u1.w) * va, vb, t1);
                }
            }
            eb += cnt;
            atomicAdd(&sout[s * (NLM * 64) + c * 64 + g], w00 * (t0 + t1));
        }
    }
    __syncthreads();
    float* yo = g_y1 + (size_t)n * (2 * NLM * 64);
    for (int q = tid; q < 2 * NLM * 64; q += 128) yo[q] = sout[q];
}

// ---- TP layer 1: 128 threads; role 0: sa + even terms; role 1: sb + odd terms ----
__global__ void __launch_bounds__(128) k_tp1(const float* __restrict__ W1,
                                             const float* __restrict__ W2,
                                             const float* __restrict__ wp) {
    __shared__ float sa[NLM * 128];   // [a][2f + p]
    __shared__ float sb[NLM * 128];
    __shared__ float sout[2 * NLM * 64];
    int n = blockIdx.x;
    int tid = threadIdx.x;
    int g = tid & 63;
    int role = tid >> 6;

    const float* yin = g_y1 + (size_t)n * (2 * NLM * 64);
    const float* Wm = role ? W2 : W1;
    float* dst = role ? sb : sa;

    for (int q = tid; q < 2 * NLM * 64; q += 128) sout[q] = 0.0f;

    for (int p = 0; p < 2; p++) {
        for (int d = 0; d < 5; d++) {
            float w[64];
            const float* Wb = Wm + ((p * 5 + d) * 64) * 64 + g;
#pragma unroll
            for (int f = 0; f < 64; f++) w[f] = Wb[f * 64];
            for (int lm = d * d; lm < (d + 1) * (d + 1); lm++) {
                const float4* s4 = (const float4*)(yin + (p * NLM + lm) * 64);
                float a0 = 0.f, a1 = 0.f, a2 = 0.f, a3 = 0.f;
#pragma unroll
                for (int k = 0; k < 16; k++) {
                    float4 v = s4[k];
                    a0 = fmaf(v.x, w[4*k+0], a0);
                    a1 = fmaf(v.y, w[4*k+1], a1);
                    a2 = fmaf(v.z, w[4*k+2], a2);
                    a3 = fmaf(v.w, w[4*k+3], a3);
                }
                dst[lm * 128 + 2 * g + p] = (a0 + a1) + (a2 + a3);
            }
        }
    }
    __syncthreads();

    const char* sab = (const char*)sa + 8 * g;
    const char* sbb = (const char*)sb + 8 * g;

    if (role == 0) {
        // even terms: t00 (x), t11 (y) -> out row s with (w00, w11)
        for (int p = 0; p < NPATH; p++) {
            float wx = wp[p * 256 + g];        // w00
            float wy = wp[p * 256 + 192 + g];  // w11
            int s = g_pathS[p];
            int eb = p * PENT_STRIDE;
            int ns = g_psegcnt[p];
            for (int sg = 0; sg < ns; sg++) {
                int sc = g_pseg[p * SEG_STRIDE + sg];
                int c = sc & 255, cnt = sc >> 8;
                const int4* ge = (const int4*)(g_pent + eb);
                float2 t = make_float2(0.f, 0.f);
                for (int k = 0; k < cnt; k += 4) {
                    int4 u0 = ge[k >> 1];
                    int4 u1 = ge[(k >> 1) + 1];
                    {
                        float2 av = *(const float2*)(sab + 2 * (u0.x & 0xFFFF));
                        float2 bv = *(const float2*)(sbb + 2 * (u0.x >> 16));
                        float cg = __int_as_float(u0.y);
                        fma2_(t, mul2_(make_float2(cg, cg), av), bv);
                    }
                    {
                        float2 av = *(const float2*)(sab + 2 * (u0.z & 0xFFFF));
                        float2 bv = *(const float2*)(sbb + 2 * (u0.z >> 16));
                        float cg = __int_as_float(u0.w);
                        fma2_(t, mul2_(make_float2(cg, cg), av), bv);
                    }
                    {
                        float2 av = *(const float2*)(sab + 2 * (u1.x & 0xFFFF));
                        float2 bv = *(const float2*)(sbb + 2 * (u1.x >> 16));
                        float cg = __int_as_float(u1.y);
                        fma2_(t, mul2_(make_float2(cg, cg), av), bv);
                    }
                    {
                        float2 av = *(const float2*)(sab + 2 * (u1.z & 0xFFFF));
                        float2 bv = *(const float2*)(sbb + 2 * (u1.z >> 16));
                        float cg = __int_as_float(u1.w);
                        fma2_(t, mul2_(make_float2(cg, cg), av), bv);
                    }
                }
                eb += cnt;
                atomicAdd(&sout[s * (NLM * 64) + c * 64 + g], fmaf(wy, t.y, wx * t.x));
            }
        }
    } else {
        // odd terms: t01 = a0*b1 (x), t10 = a1*b0 (y) -> out row 1-s with (w01, w10)
        for (int p = 0; p < NPATH; p++) {
            float wx = wp[p * 256 + 64 + g];   // w01
            float wy = wp[p * 256 + 128 + g];  // w10
            int s = g_pathS[p];
            int eb = p * PENT_STRIDE;
            int ns = g_psegcnt[p];
            for (int sg = 0; sg < ns; sg++) {
                int sc = g_pseg[p * SEG_STRIDE + sg];
                int c = sc & 255, cnt = sc >> 8;
                const int4* ge = (const int4*)(g_pent + eb);
                float2 t = make_float2(0.f, 0.f);
                for (int k = 0; k < cnt; k += 4) {
                    int4 u0 = ge[k >> 1];
                    int4 u1 = ge[(k >> 1) + 1];
                    {
                        float2 av = *(const float2*)(sab + 2 * (u0.x & 0xFFFF));
                        float2 bv = *(const float2*)(sbb + 2 * (u0.x >> 16));
                        float cg = __int_as_float(u0.y);
                        fma2_(t, mul2_(make_float2(cg, cg), av), make_float2(bv.y, bv.x));
                    }
                    {
                        float2 av = *(const float2*)(sab + 2 * (u0.z & 0xFFFF));
                        float2 bv = *(const float2*)(sbb + 2 * (u0.z >> 16));
                        float cg = __int_as_float(u0.w);
                        fma2_(t, mul2_(make_float2(cg, cg), av), make_float2(bv.y, bv.x));
                    }
                    {
                        float2 av = *(const float2*)(sab + 2 * (u1.x & 0xFFFF));
                        float2 bv = *(const float2*)(sbb + 2 * (u1.x >> 16));
                        float cg = __int_as_float(u1.y);
                        fma2_(t, mul2_(make_float2(cg, cg), av), make_float2(bv.y, bv.x));
                    }
                    {
                        float2 av = *(const float2*)(sab + 2 * (u1.z & 0xFFFF));
                        float2 bv = *(const float2*)(sbb + 2 * (u1.z >> 16));
                        float cg = __int_as_float(u1.w);
                        fma2_(t, mul2_(make_float2(cg, cg), av), make_float2(bv.y, bv.x));
                    }
                }
                eb += cnt;
                atomicAdd(&sout[(1 - s) * (NLM * 64) + c * 64 + g], fmaf(wy, t.y, wx * t.x));
            }
        }
    }
    __syncthreads();
    float* yo = g_y2 + (size_t)n * (2 * NLM * 64);
    for (int q = tid; q < 2 * NLM * 64; q += 128) yo[q] = sout[q];
}

// ---- final: te = emb@W_et + b_et; scale, concat, mish (exact algebraic form) ----
__global__ void __launch_bounds__(160) k_final(const int* __restrict__ Z,
                                               const float* __restrict__ emb,
                                               const float* __restrict__ W_et,
                                               const float* __restrict__ b_et,
                                               const float* __restrict__ wf,
                                               float* __restrict__ outp) {
    __shared__ float s_emb[64];
    int n = blockIdx.x;
    int t = threadIdx.x;
    if (t < 64) s_emb[t] = emb[Z[n] * 64 + t];
    __syncthreads();
    if (t >= 144) return;

    float te = b_et[t];
#pragma unroll
    for (int d = 0; d < 64; d++) te = fmaf(s_emb[d], W_et[d * 144 + t], te);

    for (int p = 0; p < 2; p++) {
        for (int lm = 0; lm < NLM; lm++) {
            float yc;
            if (t < 16)
                yc = (p == 0) ? g_y0[(size_t)n * (NLM * 16) + lm * 16 + t] : 0.0f;
            else if (t < 80)
                yc = g_y1[((size_t)n * 2 + p) * (NLM * 64) + lm * 64 + (t - 16)];
            else
                yc = g_y2[((size_t)n * 2 + p) * (NLM * 64) + lm * 64 + (t - 80)];
            float v = te * yc * wf[(p * 5 + c_deg[lm]) * 144 + t];
            if (p == 0 && lm == 0) v += te;
            // mish: v + v*tanh(softplus(v)) = v * 2u^2/(u^2+1), u = 1+e^v  (exact)
            float e = expf(fminf(v, 40.0f));
            float u = 1.0f + e;
            float u2 = u * u;
            float o = v * (2.0f * u2) / (u2 + 1.0f);
            outp[(((size_t)n * 2 + p) * NLM + lm) * 144 + t] = o;
        }
    }
}

// ---------------- launch ----------------
extern "C" void kernel_launch(void* const* d_in, const int* in_sizes, int n_in,
                              void* d_out, int out_size) {
    const int*   Z    = (const int*)d_in[0];
    const int*   nbr  = (const int*)d_in[1];
    const float* disp = (const float*)d_in[2];
    const float* Wsp  = (const float*)d_in[3];
    const float* emb  = (const float*)d_in[4];
    const float* W_et = (const float*)d_in[5];
    const float* b_et = (const float*)d_in[6];
    const float* norm = (const float*)d_in[7];
    const float* t0W1 = (const float*)d_in[8];
    const float* t0W2 = (const float*)d_in[9];
    const float* t0wp = (const float*)d_in[10];
    const float* t1W1 = (const float*)d_in[11];
    const float* t1W2 = (const float*)d_in[12];
    const float* t1wp = (const float*)d_in[13];
    const float* wfus = (const float*)d_in[14];
    float* outp = (float*)d_out;

    int N = in_sizes[0];
    int E = in_sizes[1] / 2;

    int tot4 = (N * NLM * 16) / 4;
    k_zero<<<(tot4 + 255) / 256, 256>>>(tot4);
    k_init_u<<<1, 128>>>();
    k_init_cc<<<(NLM*NLM*NLM + 255) / 256, 256>>>();
    k_edge<<<(E * 16 + 255) / 256, 256>>>(nbr, disp, Z, Wsp, norm, E);
    k_init_T<<<(NLM*NLM*NLM + 255) / 256, 256>>>();
    k_init_ents<<<NPATH, 32>>>();
    k_tp0<<<N, 128>>>(t0W1, t0W2, t0wp);
    k_tp1<<<N, 128>>>(t1W1, t1W2, t1wp);
    k_final<<<N, 160>>>(Z, emb, W_et, b_et, wfus, outp);
}

// round 6
// speedup vs baseline: 1.3536x; 1.3536x over previous
#include <cuda_runtime.h>
#include <math.h>

#define NLM 25
#define NPATH 65
#define PENT_STRIDE 320
#define SEG_STRIDE 9
#define PI_F 3.14159265358979323846f
#define CUTOFF_F 5.0f
#define MAXN 10240
#define TBLOCKS 62   // ceil(25^3 / 256)

// ---------------- scratch (static __device__, no allocations) ----------------
__device__ float  g_y0[MAXN * NLM * 16];
__device__ float  g_y1[MAXN * 2 * NLM * 64];
__device__ float  g_y2[MAXN * 2 * NLM * 64];
__device__ float  g_CG[NLM * NLM * NLM];
__device__ int2   g_pent[NPATH * PENT_STRIDE];   // (a*256 | (b*256)<<16, cg bits)
__device__ int    g_pseg[NPATH * SEG_STRIDE];    // c | cnt<<8  (cnt multiple of 4)
__device__ int    g_psegcnt[NPATH];
__device__ int    g_pathS[NPATH];                // (l1+l2+l3) & 1
__device__ int    g_pathP3[NPATH];               // l3 & 1  (role split key)

__constant__ int c_deg[NLM] = {0,1,1,1,2,2,2,2,2,3,3,3,3,3,3,3,4,4,4,4,4,4,4,4,4};

// ---------------- CG construction (exact, fp64, every launch) ----------------
__device__ __forceinline__ double dfact(int n) {
    const double f[16] = {1.0,1.0,2.0,6.0,24.0,120.0,720.0,5040.0,40320.0,
                          362880.0,3628800.0,39916800.0,479001600.0,
                          6227020800.0,87178291200.0,1307674368000.0};
    return f[n];
}

__device__ double cg_complex(int l1,int m1,int l2,int m2,int l3,int m3) {
    if (m1 + m2 != m3 || l3 < abs(l1 - l2) || l3 > l1 + l2) return 0.0;
    double P = dfact(l1+l2-l3) * dfact(l1-l2+l3) * dfact(-l1+l2+l3) / dfact(l1+l2+l3+1)
             * dfact(l1+m1) * dfact(l1-m1) * dfact(l2+m2) * dfact(l2-m2)
             * dfact(l3+m3) * dfact(l3-m3);
    double sp = sqrt(P);
    int kmin = max(0, max(l2 - l3 - m1, l1 - l3 + m2));
    int kmax = min(l1 + l2 - l3, min(l1 - m1, l2 + m2));
    double s = 0.0;
    for (int k = kmin; k <= kmax; k++) {
        double D = dfact(k) * dfact(l1+l2-l3-k) * dfact(l1-m1-k) * dfact(l2+m2-k)
                 * dfact(l3-l2+m1+k) * dfact(l3-l1-m2+k);
        s += ((k & 1) ? -1.0 : 1.0) * sp / D;
    }
    return sqrt(2.0 * l3 + 1.0) * s;
}

// nonzero columns of real<->complex transform U for row (l, m)
__device__ __forceinline__ int u_row(int l, int m, int* col, double* re, double* im) {
    int off = l * l + l;
    const double is2 = 0.7071067811865476;
    if (m == 0) { col[0] = off; re[0] = 1.0; im[0] = 0.0; return 1; }
    if (m > 0) {
        double sgn = (m & 1) ? -1.0 : 1.0;
        col[0] = off + m; re[0] = sgn * is2; im[0] = 0.0;
        col[1] = off - m; re[1] = is2;       im[1] = 0.0;
        return 2;
    }
    int mm = -m;
    double sgn = (mm & 1) ? -1.0 : 1.0;
    col[0] = off - mm; re[0] = 0.0; im[0] = is2;
    col[1] = off + mm; re[1] = 0.0; im[1] = -sgn * is2;
    return 2;
}

// blocks [0,TBLOCKS): build real CG tensor; blocks >= TBLOCKS: zero g_y0
__global__ void k_init_T(int tot4) {
    if (blockIdx.x >= TBLOCKS) {
        int t = (blockIdx.x - TBLOCKS) * blockDim.x + threadIdx.x;
        if (t < tot4) ((float4*)g_y0)[t] = make_float4(0.f, 0.f, 0.f, 0.f);
        return;
    }
    int t = blockIdx.x * blockDim.x + threadIdx.x;
    if (t >= NLM * NLM * NLM) return;
    int i = t / (NLM * NLM), j = (t / NLM) % NLM, k = t % NLM;
    int li = c_deg[i], mi = i - li * li - li;
    int lj = c_deg[j], mj = j - lj * lj - lj;
    int lk = c_deg[k], mk = k - lk * lk - lk;

    int ca[2]; double are[2], aim[2]; int na = u_row(li, mi, ca, are, aim);
    int cb[2]; double bre[2], bim[2]; int nb = u_row(lj, mj, cb, bre, bim);
    int cc[2]; double kre[2], kim[2]; int nc = u_row(lk, mk, cc, kre, kim);

    double tre = 0.0, tim = 0.0;
    for (int aa = 0; aa < na; aa++) {
        for (int bb = 0; bb < nb; bb++) {
            double wre = are[aa] * bre[bb] - aim[aa] * bim[bb];
            double wim = are[aa] * bim[bb] + aim[aa] * bre[bb];
            for (int ci = 0; ci < nc; ci++) {
                int a = ca[aa], b = cb[bb], c = cc[ci];
                double cg = cg_complex(li, a - li*li - li, lj, b - lj*lj - lj,
                                       lk, c - lk*lk - lk);
                if (cg == 0.0) continue;
                double ur3 = kre[ci], ui3 = -kim[ci];  // conj
                tre += (wre * ur3 - wim * ui3) * cg;
                tim += (wre * ui3 + wim * ur3) * cg;
            }
        }
    }
    double v = tre + tim;
    g_CG[t] = (fabs(v) < 1e-12) ? 0.0f : (float)v;
}

// warp-per-path ballot compaction; entries padded to multiples of 4
__global__ void k_init_ents() {
    int p = blockIdx.x;
    int lane = threadIdx.x;
    int l1 = 0, l2 = 0, l3 = 0, acc = 0;
    bool found = false;
    for (int a1 = 0; a1 <= 4; a1++)
        for (int a2 = 0; a2 <= 4; a2++) {
            int lo = abs(a1 - a2), hi = min(4, a1 + a2), cnt = hi - lo + 1;
            if (!found) {
                if (p < acc + cnt) { l1 = a1; l2 = a2; l3 = lo + (p - acc); found = true; }
                else acc += cnt;
            }
        }
    if (lane == 0) { g_pathS[p] = (l1 + l2 + l3) & 1; g_pathP3[p] = l3 & 1; }

    int na = 2 * l1 + 1, nb = 2 * l2 + 1, npair = na * nb;
    int a0 = l1 * l1, b0 = l2 * l2;
    int eb = p * PENT_STRIDE;
    int ne = 0, ns = 0;
    for (int c = l3 * l3; c < (l3 + 1) * (l3 + 1); c++) {
        int segstart = ne;
        for (int base = 0; base < npair; base += 32) {
            int q = base + lane;
            float v = 0.0f; int a = 0, b = 0;
            if (q < npair) {
                a = a0 + q / nb; b = b0 + q % nb;
                v = g_CG[(a * NLM + b) * NLM + c];
            }
            unsigned mask = __ballot_sync(0xffffffffu, v != 0.0f);
            if (v != 0.0f) {
                int pos = ne + __popc(mask & ((1u << lane) - 1u));
                g_pent[eb + pos] = make_int2((a * 256) | ((b * 256) << 16), __float_as_int(v));
            }
            ne += __popc(mask);
        }
        int cn = ne - segstart;
        int pad = (4 - (cn & 3)) & 3;
        if (cn > 0) {
            if (lane < pad) g_pent[eb + ne + lane] = make_int2(0, 0);
            ne += pad; cn += pad;
            if (lane == 0) g_pseg[p * SEG_STRIDE + ns] = c | (cn << 8);
            ns++;
        }
    }
    if (lane == 0) g_psegcnt[p] = ns;
}

// ---------------- edge kernel: 16 lanes/edge, one rbf exp per lane ----------------
__global__ void k_edge(const int* __restrict__ nbr, const float* __restrict__ disp,
                       const int* __restrict__ Z, const float* __restrict__ Wsp,
                       const float* __restrict__ normp, int E) {
    int t = blockIdx.x * blockDim.x + threadIdx.x;
    int e = t >> 4, lane = t & 15;
    bool valid = (e < E);
    int i = 0, j = 0;
    float dx = 0.f, dy = 0.f, dz = 1.f;
    if (valid) {
        i = nbr[2 * e]; j = nbr[2 * e + 1];
        dx = disp[3 * e]; dy = disp[3 * e + 1]; dz = disp[3 * e + 2];
    }
    float r = sqrtf(dx * dx + dy * dy + dz * dz + 1e-12f);
    float inv = 1.0f / r;
    float x = dx * inv, y = dy * inv, z = dz * inv;
    bool ok = valid && (r < CUTOFF_F);
    float fcut = 0.5f * (cosf(PI_F * fminf(r * (1.0f / CUTOFF_F), 1.0f)) + 1.0f);

    int Zj = valid ? Z[j] : 0;
    const float gamma = 10.24f;
    float d = r - (float)lane * (CUTOFF_F / 15.0f);
    float rbf = expf(-gamma * d * d);

    const float* W = Wsp + Zj * 256 + lane;
    float gsum = 0.0f;
#pragma unroll
    for (int k = 0; k < 16; k++) {
        float rb = __shfl_sync(0xffffffffu, rbf, k, 16);
        gsum = fmaf(rb, W[k * 16], gsum);
    }
    if (!ok) return;
    float g = gsum * fcut / normp[0];

    float x2 = x * x, y2 = y * y, z2 = z * z;
    float Y[NLM];
    Y[0]  = 0.5f * sqrtf(1.0f / PI_F);
    Y[1]  = sqrtf(3.0f / (4.0f * PI_F)) * y;
    Y[2]  = sqrtf(3.0f / (4.0f * PI_F)) * z;
    Y[3]  = sqrtf(3.0f / (4.0f * PI_F)) * x;
    Y[4]  = 0.5f * sqrtf(15.0f / PI_F) * x * y;
    Y[5]  = 0.5f * sqrtf(15.0f / PI_F) * y * z;
    Y[6]  = 0.25f * sqrtf(5.0f / PI_F) * (3.0f * z2 - 1.0f);
    Y[7]  = 0.5f * sqrtf(15.0f / PI_F) * x * z;
    Y[8]  = 0.25f * sqrtf(15.0f / PI_F) * (x2 - y2);
    Y[9]  = 0.25f * sqrtf(35.0f / (2.0f * PI_F)) * y * (3.0f * x2 - y2);
    Y[10] = 0.5f * sqrtf(105.0f / PI_F) * x * y * z;
    Y[11] = 0.25f * sqrtf(21.0f / (2.0f * PI_F)) * y * (5.0f * z2 - 1.0f);
    Y[12] = 0.25f * sqrtf(7.0f / PI_F) * z * (5.0f * z2 - 3.0f);
    Y[13] = 0.25f * sqrtf(21.0f / (2.0f * PI_F)) * x * (5.0f * z2 - 1.0f);
    Y[14] = 0.25f * sqrtf(105.0f / PI_F) * z * (x2 - y2);
    Y[15] = 0.25f * sqrtf(35.0f / (2.0f * PI_F)) * x * (x2 - 3.0f * y2);
    Y[16] = 0.75f * sqrtf(35.0f / PI_F) * x * y * (x2 - y2);
    Y[17] = 0.75f * sqrtf(35.0f / (2.0f * PI_F)) * y * z * (3.0f * x2 - y2);
    Y[18] = 0.75f * sqrtf(5.0f / PI_F) * x * y * (7.0f * z2 - 1.0f);
    Y[19] = 0.75f * sqrtf(5.0f / (2.0f * PI_F)) * y * z * (7.0f * z2 - 3.0f);
    Y[20] = (3.0f / 16.0f) * sqrtf(1.0f / PI_F) * (35.0f * z2 * z2 - 30.0f * z2 + 3.0f);
    Y[21] = 0.75f * sqrtf(5.0f / (2.0f * PI_F)) * x * z * (7.0f * z2 - 3.0f);
    Y[22] = (3.0f / 8.0f) * sqrtf(5.0f / PI_F) * (x2 - y2) * (7.0f * z2 - 1.0f);
    Y[23] = 0.75f * sqrtf(35.0f / (2.0f * PI_F)) * x * z * (x2 - 3.0f * y2);
    Y[24] = (3.0f / 16.0f) * sqrtf(35.0f / PI_F) * (x2 * x2 - 6.0f * x2 * y2 + y2 * y2);

    float* dst = g_y0 + (size_t)i * (NLM * 16) + lane;
#pragma unroll
    for (int lm = 0; lm < NLM; lm++)
        atomicAdd(dst + lm * 16, Y[lm] * g);
}

// ---- TP layer 0: 128 thr; dense role-split (sa/sb), product l3-parity split ----
__global__ void __launch_bounds__(128) k_tp0(const float* __restrict__ W1,
                                             const float* __restrict__ W2,
                                             const float* __restrict__ wp) {
    __shared__ float sa[NLM * 64];
    __shared__ float sb[NLM * 64];
    __shared__ float sout[2 * NLM * 64];
    int n = blockIdx.x;
    int tid = threadIdx.x;
    int g = tid & 63;
    int role = tid >> 6;

    const float* yin = g_y0 + (size_t)n * (NLM * 16);
    const float* Wm = role ? W2 : W1;
    float* dst = role ? sb : sa;

    for (int q = tid; q < 2 * NLM * 64; q += 128) sout[q] = 0.0f;

    for (int d = 0; d < 5; d++) {
        float w[16];
        const float* Wb = Wm + (d * 16) * 64 + g;
#pragma unroll
        for (int f = 0; f < 16; f++) w[f] = Wb[f * 64];
        for (int lm = d * d; lm < (d + 1) * (d + 1); lm++) {
            const float4* s4 = (const float4*)(yin + lm * 16);
            float a0 = 0.f, a1 = 0.f, a2 = 0.f, a3 = 0.f;
#pragma unroll
            for (int k = 0; k < 4; k++) {
                float4 v = s4[k];
                a0 = fmaf(v.x, w[4*k+0], a0);
                a1 = fmaf(v.y, w[4*k+1], a1);
                a2 = fmaf(v.z, w[4*k+2], a2);
                a3 = fmaf(v.w, w[4*k+3], a3);
            }
            dst[lm * 64 + g] = (a0 + a1) + (a2 + a3);
        }
    }
    __syncthreads();

    const char* sab = (const char*)sa + 4 * g;
    const char* sbb = (const char*)sb + 4 * g;
    for (int p = 0; p < NPATH; p++) {
        if (g_pathP3[p] != role) continue;   // even-l3 -> role 0, odd-l3 -> role 1
        float w00 = wp[p * 256 + g];
        int s = g_pathS[p];
        int eb = p * PENT_STRIDE;
        int ns = g_psegcnt[p];
        for (int sg = 0; sg < ns; sg++) {
            int sc = g_pseg[p * SEG_STRIDE + sg];
            int c = sc & 255, cnt = sc >> 8;
            const int4* ge = (const int4*)(g_pent + eb);
            float t0 = 0.f, t1 = 0.f;
            for (int k = 0; k < cnt; k += 4) {
                int4 u0 = ge[k >> 1];
                int4 u1 = ge[(k >> 1) + 1];
                t0 = fmaf(__int_as_float(u0.y) * *(const float*)(sab + (u0.x & 0xFFFF)),
                          *(const float*)(sbb + (u0.x >> 16)), t0);
                t1 = fmaf(__int_as_float(u0.w) * *(const float*)(sab + (u0.z & 0xFFFF)),
                          *(const float*)(sbb + (u0.z >> 16)), t1);
                t0 = fmaf(__int_as_float(u1.y) * *(const float*)(sab + (u1.x & 0xFFFF)),
                          *(const float*)(sbb + (u1.x >> 16)), t0);
                t1 = fmaf(__int_as_float(u1.w) * *(const float*)(sab + (u1.z & 0xFFFF)),
                          *(const float*)(sbb + (u1.z >> 16)), t1);
            }
            eb += cnt;
            sout[s * (NLM * 64) + c * 64 + g] += w00 * (t0 + t1);  // conflict-free
        }
    }
    __syncthreads();
    float* yo = g_y1 + (size_t)n * (2 * NLM * 64);
    for (int q = tid; q < 2 * NLM * 64; q += 128) yo[q] = sout[q];
}

// ---- TP layer 1: full 2-parity product; same split strategy ----
__global__ void __launch_bounds__(128) k_tp1(const float* __restrict__ W1,
                                             const float* __restrict__ W2,
                                             const float* __restrict__ wp) {
    __shared__ float sa[NLM * 128];   // [a][2f + p]
    __shared__ float sb[NLM * 128];
    __shared__ float sout[2 * NLM * 64];
    int n = blockIdx.x;
    int tid = threadIdx.x;
    int g = tid & 63;
    int role = tid >> 6;

    const float* yin = g_y1 + (size_t)n * (2 * NLM * 64);
    const float* Wm = role ? W2 : W1;
    float* dst = role ? sb : sa;

    for (int q = tid; q < 2 * NLM * 64; q += 128) sout[q] = 0.0f;

    for (int p = 0; p < 2; p++) {
        for (int d = 0; d < 5; d++) {
            float w[64];
            const float* Wb = Wm + ((p * 5 + d) * 64) * 64 + g;
#pragma unroll
            for (int f = 0; f < 64; f++) w[f] = Wb[f * 64];
            for (int lm = d * d; lm < (d + 1) * (d + 1); lm++) {
                const float4* s4 = (const float4*)(yin + (p * NLM + lm) * 64);
                float a0 = 0.f, a1 = 0.f, a2 = 0.f, a3 = 0.f;
#pragma unroll
                for (int k = 0; k < 16; k++) {
                    float4 v = s4[k];
                    a0 = fmaf(v.x, w[4*k+0], a0);
                    a1 = fmaf(v.y, w[4*k+1], a1);
                    a2 = fmaf(v.z, w[4*k+2], a2);
                    a3 = fmaf(v.w, w[4*k+3], a3);
                }
                dst[lm * 128 + 2 * g + p] = (a0 + a1) + (a2 + a3);
            }
        }
    }
    __syncthreads();

    const char* sab = (const char*)sa + 8 * g;
    const char* sbb = (const char*)sb + 8 * g;

    for (int p = 0; p < NPATH; p++) {
        if (g_pathP3[p] != role) continue;
        float w00 = wp[p * 256 + g];
        float w01 = wp[p * 256 + 64 + g];
        float w10 = wp[p * 256 + 128 + g];
        float w11 = wp[p * 256 + 192 + g];
        int s = g_pathS[p];
        int eb = p * PENT_STRIDE;
        int ns = g_psegcnt[p];
        for (int sg = 0; sg < ns; sg++) {
            int sc = g_pseg[p * SEG_STRIDE + sg];
            int c = sc & 255, cnt = sc >> 8;
            const int4* ge = (const int4*)(g_pent + eb);
            float t00 = 0.f, t01 = 0.f, t10 = 0.f, t11 = 0.f;
            for (int k = 0; k < cnt; k += 4) {
                int4 u0 = ge[k >> 1];
                int4 u1 = ge[(k >> 1) + 1];
                {
                    float2 av = *(const float2*)(sab + 2 * (u0.x & 0xFFFF));
                    float2 bv = *(const float2*)(sbb + 2 * (u0.x >> 16));
                    float cg = __int_as_float(u0.y);
                    float ca0 = cg * av.x, ca1 = cg * av.y;
                    t00 = fmaf(ca0, bv.x, t00); t11 = fmaf(ca1, bv.y, t11);
                    t01 = fmaf(ca0, bv.y, t01); t10 = fmaf(ca1, bv.x, t10);
                }
                {
                    float2 av = *(const float2*)(sab + 2 * (u0.z & 0xFFFF));
                    float2 bv = *(const float2*)(sbb + 2 * (u0.z >> 16));
                    float cg = __int_as_float(u0.w);
                    float ca0 = cg * av.x, ca1 = cg * av.y;
                    t00 = fmaf(ca0, bv.x, t00); t11 = fmaf(ca1, bv.y, t11);
                    t01 = fmaf(ca0, bv.y, t01); t10 = fmaf(ca1, bv.x, t10);
                }
                {
                    float2 av = *(const float2*)(sab + 2 * (u1.x & 0xFFFF));
                    float2 bv = *(const float2*)(sbb + 2 * (u1.x >> 16));
                    float cg = __int_as_float(u1.y);
                    float ca0 = cg * av.x, ca1 = cg * av.y;
                    t00 = fmaf(ca0, bv.x, t00); t11 = fmaf(ca1, bv.y, t11);
                    t01 = fmaf(ca0, bv.y, t01); t10 = fmaf(ca1, bv.x, t10);
                }
                {
                    float2 av = *(const float2*)(sab + 2 * (u1.z & 0xFFFF));
                    float2 bv = *(const float2*)(sbb + 2 * (u1.z >> 16));
                    float cg = __int_as_float(u1.w);
                    float ca0 = cg * av.x, ca1 = cg * av.y;
                    t00 = fmaf(ca0, bv.x, t00); t11 = fmaf(ca1, bv.y, t11);
                    t01 = fmaf(ca0, bv.y, t01); t10 = fmaf(ca1, bv.x, t10);
                }
            }
            eb += cnt;
            sout[s * (NLM * 64) + c * 64 + g]       += fmaf(w11, t11, w00 * t00);
            sout[(1 - s) * (NLM * 64) + c * 64 + g] += fmaf(w10, t10, w01 * t01);
        }
    }
    __syncthreads();
    float* yo = g_y2 + (size_t)n * (2 * NLM * 64);
    for (int q = tid; q < 2 * NLM * 64; q += 128) yo[q] = sout[q];
}

// ---- final: te = emb@W_et + b_et; scale, concat, mish (algebraic form) ----
__global__ void __launch_bounds__(160) k_final(const int* __restrict__ Z,
                                               const float* __restrict__ emb,
                                               const float* __restrict__ W_et,
                                               const float* __restrict__ b_et,
                                               const float* __restrict__ wf,
                                               float* __restrict__ outp) {
    __shared__ float s_emb[64];
    int n = blockIdx.x;
    int t = threadIdx.x;
    if (t < 64) s_emb[t] = emb[Z[n] * 64 + t];
    __syncthreads();
    if (t >= 144) return;

    float te = b_et[t];
#pragma unroll
    for (int d = 0; d < 64; d++) te = fmaf(s_emb[d], W_et[d * 144 + t], te);

    for (int p = 0; p < 2; p++) {
        for (int lm = 0; lm < NLM; lm++) {
            float yc;
            if (t < 16)
                yc = (p == 0) ? g_y0[(size_t)n * (NLM * 16) + lm * 16 + t] : 0.0f;
            else if (t < 80)
                yc = g_y1[((size_t)n * 2 + p) * (NLM * 64) + lm * 64 + (t - 16)];
            else
                yc = g_y2[((size_t)n * 2 + p) * (NLM * 64) + lm * 64 + (t - 80)];
            float v = te * yc * wf[(p * 5 + c_deg[lm]) * 144 + t];
            if (p == 0 && lm == 0) v += te;
            // mish: v + v*tanh(softplus(v)) = v * 2u^2/(u^2+1), u = 1+e^v
            float e = expf(fminf(v, 40.0f));
            float u = 1.0f + e;
            float u2 = u * u;
            float o = v * (2.0f * u2) / (u2 + 1.0f);
            outp[(((size_t)n * 2 + p) * NLM + lm) * 144 + t] = o;
        }
    }
}

// ---------------- launch ----------------
extern "C" void kernel_launch(void* const* d_in, const int* in_sizes, int n_in,
                              void* d_out, int out_size) {
    const int*   Z    = (const int*)d_in[0];
    const int*   nbr  = (const int*)d_in[1];
    const float* disp = (const float*)d_in[2];
    const float* Wsp  = (const float*)d_in[3];
    const float* emb  = (const float*)d_in[4];
    const float* W_et = (const float*)d_in[5];
    const float* b_et = (const float*)d_in[6];
    const float* norm = (const float*)d_in[7];
    const float* t0W1 = (const float*)d_in[8];
    const float* t0W2 = (const float*)d_in[9];
    const float* t0wp = (const float*)d_in[10];
    const float* t1W1 = (const float*)d_in[11];
    const float* t1W2 = (const float*)d_in[12];
    const float* t1wp = (const float*)d_in[13];
    const float* wfus = (const float*)d_in[14];
    float* outp = (float*)d_out;

    int N = in_sizes[0];
    int E = in_sizes[1] / 2;

    int tot4 = (N * NLM * 16) / 4;
    int zb = (tot4 + 255) / 256;
    k_init_T<<<TBLOCKS + zb, 256>>>(tot4);          // launch 1 (CG + zero y0)
    k_init_ents<<<NPATH, 32>>>();                   // launch 2
    k_edge<<<(E * 16 + 255) / 256, 256>>>(nbr, disp, Z, Wsp, norm, E);  // launch 3
    k_tp0<<<N, 128>>>(t0W1, t0W2, t0wp);            // launch 4  <- profiled slot
    k_tp1<<<N, 128>>>(t1W1, t1W2, t1wp);            // launch 5
    k_final<<<N, 160>>>(Z, emb, W_et, b_et, wfus, outp);  // launch 6
}

// round 7
// speedup vs baseline: 1.9590x; 1.4472x over previous
#include <cuda_runtime.h>
#include <math.h>

#define NLM 25
#define NPATH 65
#define PENT_STRIDE 320
#define SEG_STRIDE 9
#define RSEG_STRIDE 128
#define PI_F 3.14159265358979323846f
#define CUTOFF_F 5.0f
#define MAXN 10240
#define TBLOCKS 62   // ceil(25^3 / 256)

// ---------------- scratch (static __device__, no allocations) ----------------
__device__ float  g_y0[MAXN * NLM * 16];
__device__ float  g_y1[MAXN * 2 * NLM * 64];
__device__ float  g_y2[MAXN * 2 * NLM * 64];
__device__ float  g_CG[NLM * NLM * NLM];
__device__ int2   g_pent[NPATH * PENT_STRIDE];    // (a*256 | (b*256)<<16, cg bits)  [tp0: 64-f rows]
__device__ int2   g_pent2[NPATH * PENT_STRIDE];   // (a*512 | (b*512)<<16, cg bits)  [tp1: 128-f rows]
__device__ int    g_pseg[NPATH * SEG_STRIDE];     // c | cnt<<8  (cnt multiple of 4)
__device__ int    g_psegcnt[NPATH];
__device__ int    g_pathS[NPATH];                 // (l1+l2+l3) & 1
__device__ int2   g_rseg[4 * RSEG_STRIDE];        // x: entry_off | cnt<<20 ; y: c | s<<5 | path<<6
__device__ int    g_rsegcnt[4];

__constant__ int c_deg[NLM] = {0,1,1,1,2,2,2,2,2,3,3,3,3,3,3,3,4,4,4,4,4,4,4,4,4};

// ---------------- CG construction (exact, fp64, every launch) ----------------
__device__ __forceinline__ double dfact(int n) {
    const double f[16] = {1.0,1.0,2.0,6.0,24.0,120.0,720.0,5040.0,40320.0,
                          362880.0,3628800.0,39916800.0,479001600.0,
                          6227020800.0,87178291200.0,1307674368000.0};
    return f[n];
}

__device__ double cg_complex(int l1,int m1,int l2,int m2,int l3,int m3) {
    if (m1 + m2 != m3 || l3 < abs(l1 - l2) || l3 > l1 + l2) return 0.0;
    double P = dfact(l1+l2-l3) * dfact(l1-l2+l3) * dfact(-l1+l2+l3) / dfact(l1+l2+l3+1)
             * dfact(l1+m1) * dfact(l1-m1) * dfact(l2+m2) * dfact(l2-m2)
             * dfact(l3+m3) * dfact(l3-m3);
    double sp = sqrt(P);
    int kmin = max(0, max(l2 - l3 - m1, l1 - l3 + m2));
    int kmax = min(l1 + l2 - l3, min(l1 - m1, l2 + m2));
    double s = 0.0;
    for (int k = kmin; k <= kmax; k++) {
        double D = dfact(k) * dfact(l1+l2-l3-k) * dfact(l1-m1-k) * dfact(l2+m2-k)
                 * dfact(l3-l2+m1+k) * dfact(l3-l1-m2+k);
        s += ((k & 1) ? -1.0 : 1.0) * sp / D;
    }
    return sqrt(2.0 * l3 + 1.0) * s;
}

__device__ __forceinline__ int u_row(int l, int m, int* col, double* re, double* im) {
    int off = l * l + l;
    const double is2 = 0.7071067811865476;
    if (m == 0) { col[0] = off; re[0] = 1.0; im[0] = 0.0; return 1; }
    if (m > 0) {
        double sgn = (m & 1) ? -1.0 : 1.0;
        col[0] = off + m; re[0] = sgn * is2; im[0] = 0.0;
        col[1] = off - m; re[1] = is2;       im[1] = 0.0;
        return 2;
    }
    int mm = -m;
    double sgn = (mm & 1) ? -1.0 : 1.0;
    col[0] = off - mm; re[0] = 0.0; im[0] = is2;
    col[1] = off + mm; re[1] = 0.0; im[1] = -sgn * is2;
    return 2;
}

// blocks [0,TBLOCKS): build real CG tensor; blocks >= TBLOCKS: zero g_y0
__global__ void k_init_T(int tot4) {
    if (blockIdx.x >= TBLOCKS) {
        int t = (blockIdx.x - TBLOCKS) * blockDim.x + threadIdx.x;
        if (t < tot4) ((float4*)g_y0)[t] = make_float4(0.f, 0.f, 0.f, 0.f);
        return;
    }
    int t = blockIdx.x * blockDim.x + threadIdx.x;
    if (t >= NLM * NLM * NLM) return;
    int i = t / (NLM * NLM), j = (t / NLM) % NLM, k = t % NLM;
    int li = c_deg[i], mi = i - li * li - li;
    int lj = c_deg[j], mj = j - lj * lj - lj;
    int lk = c_deg[k], mk = k - lk * lk - lk;

    int ca[2]; double are[2], aim[2]; int na = u_row(li, mi, ca, are, aim);
    int cb[2]; double bre[2], bim[2]; int nb = u_row(lj, mj, cb, bre, bim);
    int cc[2]; double kre[2], kim[2]; int nc = u_row(lk, mk, cc, kre, kim);

    double tre = 0.0, tim = 0.0;
    for (int aa = 0; aa < na; aa++) {
        for (int bb = 0; bb < nb; bb++) {
            double wre = are[aa] * bre[bb] - aim[aa] * bim[bb];
            double wim = are[aa] * bim[bb] + aim[aa] * bre[bb];
            for (int ci = 0; ci < nc; ci++) {
                int a = ca[aa], b = cb[bb], c = cc[ci];
                double cg = cg_complex(li, a - li*li - li, lj, b - lj*lj - lj,
                                       lk, c - lk*lk - lk);
                if (cg == 0.0) continue;
                double ur3 = kre[ci], ui3 = -kim[ci];
                tre += (wre * ur3 - wim * ui3) * cg;
                tim += (wre * ui3 + wim * ur3) * cg;
            }
        }
    }
    double v = tre + tim;
    g_CG[t] = (fabs(v) < 1e-12) ? 0.0f : (float)v;
}

// warp-per-path ballot compaction; entries padded to multiples of 4
__global__ void k_init_ents() {
    int p = blockIdx.x;
    int lane = threadIdx.x;
    int l1 = 0, l2 = 0, l3 = 0, acc = 0;
    bool found = false;
    for (int a1 = 0; a1 <= 4; a1++)
        for (int a2 = 0; a2 <= 4; a2++) {
            int lo = abs(a1 - a2), hi = min(4, a1 + a2), cnt = hi - lo + 1;
            if (!found) {
                if (p < acc + cnt) { l1 = a1; l2 = a2; l3 = lo + (p - acc); found = true; }
                else acc += cnt;
            }
        }
    if (lane == 0) g_pathS[p] = (l1 + l2 + l3) & 1;

    int na = 2 * l1 + 1, nb = 2 * l2 + 1, npair = na * nb;
    int a0 = l1 * l1, b0 = l2 * l2;
    int eb = p * PENT_STRIDE;
    int ne = 0, ns = 0;
    for (int c = l3 * l3; c < (l3 + 1) * (l3 + 1); c++) {
        int segstart = ne;
        for (int base = 0; base < npair; base += 32) {
            int q = base + lane;
            float v = 0.0f; int a = 0, b = 0;
            if (q < npair) {
                a = a0 + q / nb; b = b0 + q % nb;
                v = g_CG[(a * NLM + b) * NLM + c];
            }
            unsigned mask = __ballot_sync(0xffffffffu, v != 0.0f);
            if (v != 0.0f) {
                int pos = ne + __popc(mask & ((1u << lane) - 1u));
                g_pent[eb + pos]  = make_int2((a * 256) | ((b * 256) << 16), __float_as_int(v));
                g_pent2[eb + pos] = make_int2((a * 512) | ((b * 512) << 16), __float_as_int(v));
            }
            ne += __popc(mask);
        }
        int cn = ne - segstart;
        int pad = (4 - (cn & 3)) & 3;
        if (cn > 0) {
            if (lane < pad) {
                g_pent[eb + ne + lane]  = make_int2(0, 0);
                g_pent2[eb + ne + lane] = make_int2(0, 0);
            }
            ne += pad; cn += pad;
            if (lane == 0) g_pseg[p * SEG_STRIDE + ns] = c | (cn << 8);
            ns++;
        }
    }
    if (lane == 0) g_psegcnt[p] = ns;
}

// serial scheduler: greedy-balance c-indices into 4 classes; build per-class segment lists
__global__ void k_init_sched() {
    if (threadIdx.x != 0) return;
    int wsum[NLM];
    for (int c = 0; c < NLM; c++) wsum[c] = 0;
    for (int p = 0; p < NPATH; p++) {
        int ns = g_psegcnt[p];
        for (int sg = 0; sg < ns; sg++) {
            int m = g_pseg[p * SEG_STRIDE + sg];
            wsum[m & 255] += (m >> 8) + 8;
        }
    }
    int csel[NLM]; bool used[NLM]; int load[4] = {0, 0, 0, 0};
    for (int c = 0; c < NLM; c++) used[c] = false;
    for (int it = 0; it < NLM; it++) {
        int best = -1, bw = -1;
        for (int c = 0; c < NLM; c++)
            if (!used[c] && wsum[c] > bw) { bw = wsum[c]; best = c; }
        int kmin = 0;
        for (int k = 1; k < 4; k++) if (load[k] < load[kmin]) kmin = k;
        csel[best] = kmin; load[kmin] += bw; used[best] = true;
    }
    int cnt4[4] = {0, 0, 0, 0};
    for (int p = 0; p < NPATH; p++) {
        int off = p * PENT_STRIDE;
        int ns = g_psegcnt[p];
        int s = g_pathS[p];
        for (int sg = 0; sg < ns; sg++) {
            int m = g_pseg[p * SEG_STRIDE + sg];
            int c = m & 255, cn = m >> 8;
            int cls = csel[c];
            g_rseg[cls * RSEG_STRIDE + cnt4[cls]] =
                make_int2(off | (cn << 20), c | (s << 5) | (p << 6));
            cnt4[cls]++;
            off += cn;
        }
    }
    for (int k = 0; k < 4; k++) g_rsegcnt[k] = cnt4[k];
}

// ---------------- edge kernel ----------------
__global__ void k_edge(const int* __restrict__ nbr, const float* __restrict__ disp,
                       const int* __restrict__ Z, const float* __restrict__ Wsp,
                       const float* __restrict__ normp, int E) {
    int t = blockIdx.x * blockDim.x + threadIdx.x;
    int e = t >> 4, lane = t & 15;
    bool valid = (e < E);
    int i = 0, j = 0;
    float dx = 0.f, dy = 0.f, dz = 1.f;
    if (valid) {
        i = nbr[2 * e]; j = nbr[2 * e + 1];
        dx = disp[3 * e]; dy = disp[3 * e + 1]; dz = disp[3 * e + 2];
    }
    float r = sqrtf(dx * dx + dy * dy + dz * dz + 1e-12f);
    float inv = 1.0f / r;
    float x = dx * inv, y = dy * inv, z = dz * inv;
    bool ok = valid && (r < CUTOFF_F);
    float fcut = 0.5f * (cosf(PI_F * fminf(r * (1.0f / CUTOFF_F), 1.0f)) + 1.0f);

    int Zj = valid ? Z[j] : 0;
    const float gamma = 10.24f;
    float d = r - (float)lane * (CUTOFF_F / 15.0f);
    float rbf = expf(-gamma * d * d);

    const float* W = Wsp + Zj * 256 + lane;
    float gsum = 0.0f;
#pragma unroll
    for (int k = 0; k < 16; k++) {
        float rb = __shfl_sync(0xffffffffu, rbf, k, 16);
        gsum = fmaf(rb, W[k * 16], gsum);
    }
    if (!ok) return;
    float g = gsum * fcut / normp[0];

    float x2 = x * x, y2 = y * y, z2 = z * z;
    float Y[NLM];
    Y[0]  = 0.5f * sqrtf(1.0f / PI_F);
    Y[1]  = sqrtf(3.0f / (4.0f * PI_F)) * y;
    Y[2]  = sqrtf(3.0f / (4.0f * PI_F)) * z;
    Y[3]  = sqrtf(3.0f / (4.0f * PI_F)) * x;
    Y[4]  = 0.5f * sqrtf(15.0f / PI_F) * x * y;
    Y[5]  = 0.5f * sqrtf(15.0f / PI_F) * y * z;
    Y[6]  = 0.25f * sqrtf(5.0f / PI_F) * (3.0f * z2 - 1.0f);
    Y[7]  = 0.5f * sqrtf(15.0f / PI_F) * x * z;
    Y[8]  = 0.25f * sqrtf(15.0f / PI_F) * (x2 - y2);
    Y[9]  = 0.25f * sqrtf(35.0f / (2.0f * PI_F)) * y * (3.0f * x2 - y2);
    Y[10] = 0.5f * sqrtf(105.0f / PI_F) * x * y * z;
    Y[11] = 0.25f * sqrtf(21.0f / (2.0f * PI_F)) * y * (5.0f * z2 - 1.0f);
    Y[12] = 0.25f * sqrtf(7.0f / PI_F) * z * (5.0f * z2 - 3.0f);
    Y[13] = 0.25f * sqrtf(21.0f / (2.0f * PI_F)) * x * (5.0f * z2 - 1.0f);
    Y[14] = 0.25f * sqrtf(105.0f / PI_F) * z * (x2 - y2);
    Y[15] = 0.25f * sqrtf(35.0f / (2.0f * PI_F)) * x * (x2 - 3.0f * y2);
    Y[16] = 0.75f * sqrtf(35.0f / PI_F) * x * y * (x2 - y2);
    Y[17] = 0.75f * sqrtf(35.0f / (2.0f * PI_F)) * y * z * (3.0f * x2 - y2);
    Y[18] = 0.75f * sqrtf(5.0f / PI_F) * x * y * (7.0f * z2 - 1.0f);
    Y[19] = 0.75f * sqrtf(5.0f / (2.0f * PI_F)) * y * z * (7.0f * z2 - 3.0f);
    Y[20] = (3.0f / 16.0f) * sqrtf(1.0f / PI_F) * (35.0f * z2 * z2 - 30.0f * z2 + 3.0f);
    Y[21] = 0.75f * sqrtf(5.0f / (2.0f * PI_F)) * x * z * (7.0f * z2 - 3.0f);
    Y[22] = (3.0f / 8.0f) * sqrtf(5.0f / PI_F) * (x2 - y2) * (7.0f * z2 - 1.0f);
    Y[23] = 0.75f * sqrtf(35.0f / (2.0f * PI_F)) * x * z * (x2 - 3.0f * y2);
    Y[24] = (3.0f / 16.0f) * sqrtf(35.0f / PI_F) * (x2 * x2 - 6.0f * x2 * y2 + y2 * y2);

    float* dst = g_y0 + (size_t)i * (NLM * 16) + lane;
#pragma unroll
    for (int lm = 0; lm < NLM; lm++)
        atomicAdd(dst + lm * 16, Y[lm] * g);
}

// ---- TP layer 0: dense role-split (2x64), product 4-warp c-class split, 2 feat/thread ----
__global__ void __launch_bounds__(128) k_tp0(const float* __restrict__ W1,
                                             const float* __restrict__ W2,
                                             const float* __restrict__ wp) {
    __shared__ __align__(16) float sa[NLM * 64];
    __shared__ __align__(16) float sb[NLM * 64];
    __shared__ __align__(16) float sout[2 * NLM * 64];
    int n = blockIdx.x;
    int tid = threadIdx.x;
    int g = tid & 63;
    int drole = tid >> 6;

    const float* yin = g_y0 + (size_t)n * (NLM * 16);
    const float* Wm = drole ? W2 : W1;
    float* dst = drole ? sb : sa;

    for (int q = tid; q < 2 * NLM * 64; q += 128) sout[q] = 0.0f;

    for (int d = 0; d < 5; d++) {
        float w[16];
        const float* Wb = Wm + (d * 16) * 64 + g;
#pragma unroll
        for (int f = 0; f < 16; f++) w[f] = Wb[f * 64];
        for (int lm = d * d; lm < (d + 1) * (d + 1); lm++) {
            const float4* s4 = (const float4*)(yin + lm * 16);
            float a0 = 0.f, a1 = 0.f, a2 = 0.f, a3 = 0.f;
#pragma unroll
            for (int k = 0; k < 4; k++) {
                float4 v = s4[k];
                a0 = fmaf(v.x, w[4*k+0], a0);
                a1 = fmaf(v.y, w[4*k+1], a1);
                a2 = fmaf(v.z, w[4*k+2], a2);
                a3 = fmaf(v.w, w[4*k+3], a3);
            }
            dst[lm * 64 + g] = (a0 + a1) + (a2 + a3);
        }
    }
    __syncthreads();

    // product: warp = class role, thread q owns features 2q, 2q+1
    int q = tid & 31;
    int role = tid >> 5;
    const char* sab = (const char*)sa + 8 * q;
    const char* sbb = (const char*)sb + 8 * q;
    int nseg = g_rsegcnt[role];
    const int2* rs = g_rseg + role * RSEG_STRIDE;
    for (int si = 0; si < nseg; si++) {
        int2 m = rs[si];
        int off = m.x & 0xFFFFF;
        int cnt = ((unsigned)m.x) >> 20;
        int c = m.y & 31, s = (m.y >> 5) & 1, p = m.y >> 6;
        const int4* ge = (const int4*)(g_pent + off);
        float2 t0 = make_float2(0.f, 0.f), t1 = make_float2(0.f, 0.f);
        for (int k = 0; k < cnt; k += 4) {
            int4 u0 = ge[k >> 1];
            int4 u1 = ge[(k >> 1) + 1];
            {
                float2 va = *(const float2*)(sab + (u0.x & 0xFFFF));
                float2 vb = *(const float2*)(sbb + (u0.x >> 16));
                float cg = __int_as_float(u0.y);
                t0.x = fmaf(cg * va.x, vb.x, t0.x); t0.y = fmaf(cg * va.y, vb.y, t0.y);
            }
            {
                float2 va = *(const float2*)(sab + (u0.z & 0xFFFF));
                float2 vb = *(const float2*)(sbb + (u0.z >> 16));
                float cg = __int_as_float(u0.w);
                t1.x = fmaf(cg * va.x, vb.x, t1.x); t1.y = fmaf(cg * va.y, vb.y, t1.y);
            }
            {
                float2 va = *(const float2*)(sab + (u1.x & 0xFFFF));
                float2 vb = *(const float2*)(sbb + (u1.x >> 16));
                float cg = __int_as_float(u1.y);
                t0.x = fmaf(cg * va.x, vb.x, t0.x); t0.y = fmaf(cg * va.y, vb.y, t0.y);
            }
            {
                float2 va = *(const float2*)(sab + (u1.z & 0xFFFF));
                float2 vb = *(const float2*)(sbb + (u1.z >> 16));
                float cg = __int_as_float(u1.w);
                t1.x = fmaf(cg * va.x, vb.x, t1.x); t1.y = fmaf(cg * va.y, vb.y, t1.y);
            }
        }
        float2 w00 = *(const float2*)(wp + p * 256 + 2 * q);
        float2* row = (float2*)&sout[(s * NLM + c) * 64 + 2 * q];
        float2 r = *row;
        r.x += w00.x * (t0.x + t1.x);
        r.y += w00.y * (t0.y + t1.y);
        *row = r;
    }
    __syncthreads();
    float* yo = g_y1 + (size_t)n * (2 * NLM * 64);
    for (int qq = tid; qq < 2 * NLM * 64; qq += 128) yo[qq] = sout[qq];
}

// ---- TP layer 1: chunked dense + 4-warp c-class product, 2 feat/thread ----
__global__ void __launch_bounds__(128) k_tp1(const float* __restrict__ W1,
                                             const float* __restrict__ W2,
                                             const float* __restrict__ wp) {
    __shared__ __align__(16) float sa[NLM * 128];   // [a][2f + p]
    __shared__ __align__(16) float sb[NLM * 128];
    __shared__ __align__(16) float sout[2 * NLM * 64];
    int n = blockIdx.x;
    int tid = threadIdx.x;
    int g = tid & 63;
    int drole = tid >> 6;

    const float* yin = g_y1 + (size_t)n * (2 * NLM * 64);
    const float* Wm = drole ? W2 : W1;
    float* dst = drole ? sb : sa;

    for (int qq = tid; qq < 2 * NLM * 64; qq += 128) sout[qq] = 0.0f;

    for (int p = 0; p < 2; p++) {
#pragma unroll
        for (int d = 0; d < 5; d++) {
            const int nlm = 2 * d + 1, lm0 = d * d;
            float accA[9], accB[9];
#pragma unroll
            for (int i = 0; i < nlm; i++) { accA[i] = 0.f; accB[i] = 0.f; }
#pragma unroll
            for (int kk = 0; kk < 4; kk++) {
                float w[16];
                const float* Wb = Wm + ((p * 5 + d) * 64 + kk * 16) * 64 + g;
#pragma unroll
                for (int f = 0; f < 16; f++) w[f] = Wb[f * 64];
#pragma unroll
                for (int i = 0; i < nlm; i++) {
                    const float4* s4 = (const float4*)(yin + (p * NLM + lm0 + i) * 64 + kk * 16);
#pragma unroll
                    for (int k2 = 0; k2 < 4; k2++) {
                        float4 v = s4[k2];
                        accA[i] = fmaf(v.x, w[4*k2+0], accA[i]);
                        accB[i] = fmaf(v.y, w[4*k2+1], accB[i]);
                        accA[i] = fmaf(v.z, w[4*k2+2], accA[i]);
                        accB[i] = fmaf(v.w, w[4*k2+3], accB[i]);
                    }
                }
            }
#pragma unroll
            for (int i = 0; i < nlm; i++)
                dst[(lm0 + i) * 128 + 2 * g + p] = accA[i] + accB[i];
        }
    }
    __syncthreads();

    // product: warp role, thread q owns features 2q, 2q+1 (both parities -> float4)
    int q = tid & 31;
    int role = tid >> 5;
    const char* sab = (const char*)sa + 16 * q;
    const char* sbb = (const char*)sb + 16 * q;
    int nseg = g_rsegcnt[role];
    const int2* rs = g_rseg + role * RSEG_STRIDE;
    for (int si = 0; si < nseg; si++) {
        int2 m = rs[si];
        int off = m.x & 0xFFFFF;
        int cnt = ((unsigned)m.x) >> 20;
        int c = m.y & 31, s = (m.y >> 5) & 1, p = m.y >> 6;
        const int4* ge = (const int4*)(g_pent2 + off);
        float2 t00 = make_float2(0.f, 0.f), t01 = make_float2(0.f, 0.f);
        float2 t10 = make_float2(0.f, 0.f), t11 = make_float2(0.f, 0.f);
        for (int k = 0; k < cnt; k += 4) {
            int4 u0 = ge[k >> 1];
            int4 u1 = ge[(k >> 1) + 1];
#pragma unroll
            for (int ee = 0; ee < 4; ee++) {
                int ux = (ee == 0) ? u0.x : (ee == 1) ? u0.z : (ee == 2) ? u1.x : u1.z;
                int uy = (ee == 0) ? u0.y : (ee == 1) ? u0.w : (ee == 2) ? u1.y : u1.w;
                float4 av = *(const float4*)(sab + (ux & 0xFFFF));
                float4 bv = *(const float4*)(sbb + (ux >> 16));
                float cg = __int_as_float(uy);
                float c00 = cg * av.x, c01 = cg * av.y;
                float c10 = cg * av.z, c11 = cg * av.w;
                t00.x = fmaf(c00, bv.x, t00.x); t11.x = fmaf(c01, bv.y, t11.x);
                t01.x = fmaf(c00, bv.y, t01.x); t10.x = fmaf(c01, bv.x, t10.x);
                t00.y = fmaf(c10, bv.z, t00.y); t11.y = fmaf(c11, bv.w, t11.y);
                t01.y = fmaf(c10, bv.w, t01.y); t10.y = fmaf(c11, bv.z, t10.y);
            }
        }
        const float* wpb = wp + p * 256 + 2 * q;
        float2 w00 = *(const float2*)(wpb);
        float2 w01 = *(const float2*)(wpb + 64);
        float2 w10 = *(const float2*)(wpb + 128);
        float2 w11 = *(const float2*)(wpb + 192);
        float2* rowE = (float2*)&sout[(s * NLM + c) * 64 + 2 * q];
        float2* rowO = (float2*)&sout[((1 - s) * NLM + c) * 64 + 2 * q];
        float2 re = *rowE;
        re.x += fmaf(w11.x, t11.x, w00.x * t00.x);
        re.y += fmaf(w11.y, t11.y, w00.y * t00.y);
        *rowE = re;
        float2 ro = *rowO;
        ro.x += fmaf(w10.x, t10.x, w01.x * t01.x);
        ro.y += fmaf(w10.y, t10.y, w01.y * t01.y);
        *rowO = ro;
    }
    __syncthreads();
    float* yo = g_y2 + (size_t)n * (2 * NLM * 64);
    for (int qq = tid; qq < 2 * NLM * 64; qq += 128) yo[qq] = sout[qq];
}

// ---- final: te = emb@W_et + b_et; scale, concat, mish ----
__global__ void __launch_bounds__(160) k_final(const int* __restrict__ Z,
                                               const float* __restrict__ emb,
                                               const float* __restrict__ W_et,
                                               const float* __restrict__ b_et,
                                               const float* __restrict__ wf,
                                               float* __restrict__ outp) {
    __shared__ float s_emb[64];
    int n = blockIdx.x;
    int t = threadIdx.x;
    if (t < 64) s_emb[t] = emb[Z[n] * 64 + t];
    __syncthreads();
    if (t >= 144) return;

    float te = b_et[t];
#pragma unroll
    for (int d = 0; d < 64; d++) te = fmaf(s_emb[d], W_et[d * 144 + t], te);

    for (int p = 0; p < 2; p++) {
        for (int lm = 0; lm < NLM; lm++) {
            float yc;
            if (t < 16)
                yc = (p == 0) ? g_y0[(size_t)n * (NLM * 16) + lm * 16 + t] : 0.0f;
            else if (t < 80)
                yc = g_y1[((size_t)n * 2 + p) * (NLM * 64) + lm * 64 + (t - 16)];
            else
                yc = g_y2[((size_t)n * 2 + p) * (NLM * 64) + lm * 64 + (t - 80)];
            float v = te * yc * wf[(p * 5 + c_deg[lm]) * 144 + t];
            if (p == 0 && lm == 0) v += te;
            float e = expf(fminf(v, 40.0f));
            float u = 1.0f + e;
            float u2 = u * u;
            float o = v * (2.0f * u2) / (u2 + 1.0f);
            outp[(((size_t)n * 2 + p) * NLM + lm) * 144 + t] = o;
        }
    }
}

// ---------------- launch ----------------
extern "C" void kernel_launch(void* const* d_in, const int* in_sizes, int n_in,
                              void* d_out, int out_size) {
    const int*   Z    = (const int*)d_in[0];
    const int*   nbr  = (const int*)d_in[1];
    const float* disp = (const float*)d_in[2];
    const float* Wsp  = (const float*)d_in[3];
    const float* emb  = (const float*)d_in[4];
    const float* W_et = (const float*)d_in[5];
    const float* b_et = (const float*)d_in[6];
    const float* norm = (const float*)d_in[7];
    const float* t0W1 = (const float*)d_in[8];
    const float* t0W2 = (const float*)d_in[9];
    const float* t0wp = (const float*)d_in[10];
    const float* t1W1 = (const float*)d_in[11];
    const float* t1W2 = (const float*)d_in[12];
    const float* t1wp = (const float*)d_in[13];
    const float* wfus = (const float*)d_in[14];
    float* outp = (float*)d_out;

    int N = in_sizes[0];
    int E = in_sizes[1] / 2;

    int tot4 = (N * NLM * 16) / 4;
    int zb = (tot4 + 255) / 256;
    k_init_T<<<TBLOCKS + zb, 256>>>(tot4);                              // 1
    k_init_ents<<<NPATH, 32>>>();                                       // 2
    k_init_sched<<<1, 32>>>();                                          // 3
    k_edge<<<(E * 16 + 255) / 256, 256>>>(nbr, disp, Z, Wsp, norm, E);  // 4
    k_tp0<<<N, 128>>>(t0W1, t0W2, t0wp);                                // 5
    k_tp1<<<N, 128>>>(t1W1, t1W2, t1wp);                                // 6  <- profiled slot
    k_final<<<N, 160>>>(Z, emb, W_et, b_et, wfus, outp);                // 7
}